// round 10
// baseline (speedup 1.0000x reference)
#include <cuda_runtime.h>
#include <cstdint>

// ---------------- problem constants ----------------
#define NB 4
#define CDIM 384
#define CQ 192
#define IH 256
#define IW 256
#define H2 128
#define W2 128
#define NHEADS 8
#define HD 24
#define ATT_SCALE 0.2041241452319315f   // 24^-0.5

constexpr int HW  = IH * IW;   // 65536
constexpr int HW2 = H2 * W2;   // 16384
constexpr int NWIN = NB * 1024; // 4096 windows
constexpr int MS_W = NHEADS * HD * HD;  // 4608 floats per window

// ---------------- scratch (device globals; no runtime alloc) ----------------
__device__ float g_We[CDIM * CDIM];          // DWT-folded kv weights, tf32-rounded
__device__ float g_qw[CQ * CDIM];            // q weights, tf32-rounded
__device__ float g_pw[CDIM * CQ];            // proj weights, fragment-order tf32
__device__ float g_qfeat[(size_t)NB * CQ * HW];
__device__ float g_kv[(size_t)NB * CDIM * HW2];
__device__ float g_Ms[(size_t)NWIN * MS_W];  // per-window M matrices (75.5 MB)

// ---------------- helpers ----------------
__device__ __forceinline__ uint32_t f2tf32(float f) {
    uint32_t r;
    asm("cvt.rna.tf32.f32 %0, %1;" : "=r"(r) : "f"(f));
    return r;
}
__device__ __forceinline__ uint32_t smem_u32(const void* p) {
    uint32_t a;
    asm("{ .reg .u64 t; cvta.to.shared.u64 t, %1; cvt.u32.u64 %0, t; }" : "=r"(a) : "l"(p));
    return a;
}
__device__ __forceinline__ void cp_async16(uint32_t dst, const float* src) {
    asm volatile("cp.async.ca.shared.global [%0], [%1], 16;"
                 :: "r"(dst), "l"(__cvta_generic_to_global(src)));
}
#define CP_COMMIT() asm volatile("cp.async.commit_group;" ::: "memory")
#define CP_WAIT0()  asm volatile("cp.async.wait_group 0;"  ::: "memory")
#define CP_WAIT1()  asm volatile("cp.async.wait_group 1;"  ::: "memory")

// m16n8k8 tf32 mma (baseline PTX, sm_80+)
__device__ __forceinline__ void mma8(float* c, const uint32_t* a, const uint32_t* b) {
    asm volatile(
        "mma.sync.aligned.m16n8k8.row.col.f32.tf32.tf32.f32 "
        "{%0,%1,%2,%3}, {%4,%5,%6,%7}, {%8,%9}, {%0,%1,%2,%3};"
        : "+f"(c[0]), "+f"(c[1]), "+f"(c[2]), "+f"(c[3])
        : "r"(a[0]), "r"(a[1]), "r"(a[2]), "r"(a[3]), "r"(b[0]), "r"(b[1]));
}

// ---------------- prep: fold Haar DWT into kv weights (tf32-rounded) ----------------
__global__ void prep_we_kernel(const float* __restrict__ kvw) {
    int idx = blockIdx.x * blockDim.x + threadIdx.x;
    if (idx >= CDIM * CDIM) return;
    int ch  = idx / CDIM;
    int rem = idx - ch * CDIM;
    int c4  = rem & ~3;
    int pos = rem & 3;
    const float* w = kvw + (size_t)ch * CDIM + c4;
    float a = w[0], b = w[1], c = w[2], d = w[3];
    float r;
    if      (pos == 0) r = 0.5f * ( a - b - c + d);
    else if (pos == 1) r = 0.5f * ( a - b + c - d);
    else if (pos == 2) r = 0.5f * ( a + b - c - d);
    else               r = 0.5f * ( a + b + c + d);
    g_We[idx] = __uint_as_float(f2tf32(r));
}

// ---------------- prep: tf32-round a weight matrix ----------------
__global__ void prep_cvt_kernel(const float* __restrict__ src, float* __restrict__ dst, int n) {
    int i = blockIdx.x * blockDim.x + threadIdx.x;
    if (i < n) dst[i] = __uint_as_float(f2tf32(src[i]));
}

// ---------------- prep: rearrange weights into mma-fragment order + tf32 round ----
// [chunk c][m16-tile][lane][4 regs]; reg order {(g,tig),(g+8,tig),(g,tig+4),(g+8,tig+4)}
template<int BM, int KTOT>
__global__ void prep_arrange(const float* __restrict__ src, float* __restrict__ dst, int mtot) {
    int idx = blockIdx.x * blockDim.x + threadIdx.x;
    if (idx >= mtot * KTOT) return;
    int r    = idx % (BM * KTOT);
    int c    = r / (BM * 32);
    int t    = r % (BM * 32);
    int tile = t >> 7;
    int lane = (t >> 2) & 31;
    int qq   = t & 3;
    int wmi = tile >> 2, ks = tile & 3;
    int row = wmi * 16 + (lane >> 2) + (qq & 1) * 8;
    int kk  = c * 32 + ks * 8 + (lane & 3) + (qq >> 1) * 4;
    dst[idx] = __uint_as_float(f2tf32(src[(size_t)row * KTOT + kk]));
}

// ---------------- tf32 mma.sync GEMM (q / kv): proven R7 core ----------------
// A (pre-tf32 weights): cp.async gmem->smem [BM][36]. B: register-staged, smem [32][68].
// 2-stage pipeline, 2 CTA/SM.
template<int WARPS_M, int KTOT, int MODE, int MTOT, bool BIAS>
__global__ __launch_bounds__(256, 2) void mma_gemm(
    const float* __restrict__ Wt, const float* __restrict__ X,
    float* __restrict__ Y, const float* __restrict__ bias, int N)
{
    constexpr int BM      = 48 * WARPS_M;
    constexpr int WARPS_N = 8 / WARPS_M;
    constexpr int WN      = 64 / WARPS_N;
    constexpr int NTW     = WN / 8;
    constexpr int MT      = 3;
    constexpr int NCH     = KTOT / 32;
    constexpr int ANF     = BM / 32;
    constexpr int AFL     = BM * 36;
    constexpr int BUFL    = AFL + 32 * 68;

    extern __shared__ __align__(16) float sm[];
    const uint32_t sbase = smem_u32(sm);
    const int tid = threadIdx.x, wid = tid >> 5, lane = tid & 31;
    const int wm = wid / WARPS_N, wn = wid % WARPS_N;
    const int g = lane >> 2, tig = lane & 3;

    const float *Wp, *Xp;
    float* Yp;
    const float* bp = bias;
    int y2 = 0, xb = 0;
    const int n0 = blockIdx.x * 64;

    if (MODE == 0) {
        int b = blockIdx.z, moff = blockIdx.y * BM;
        Wp = Wt + (size_t)moff * KTOT;
        Xp = X + (size_t)b * KTOT * N;
        Yp = Y + ((size_t)b * MTOT + moff) * N;
        if (BIAS) bp = bias + moff;
    } else {
        int b = blockIdx.z >> 2, gg = blockIdx.z & 3;
        Wp = Wt + (size_t)gg * 96 * CDIM;
        Xp = X + ((size_t)b * CDIM + gg * 96) * HW;
        Yp = Y + ((size_t)b * CDIM + gg * 96) * HW2;
        y2 = n0 >> 7; xb = n0 & 127;
    }

    float acc[MT][NTW][4] = {};
    float4 bR[2];
    float  bS[8];

    auto loadA = [&](int c, int buf) {
        const int k0 = c * 32;
        const uint32_t As = sbase + (uint32_t)buf * BUFL * 4;
        #pragma unroll
        for (int i = 0; i < ANF; i++) {
            int e = tid + i * 256;
            int m = e >> 3, c4 = (e & 7) * 4;
            cp_async16(As + (m * 36 + c4) * 4, Wp + (size_t)m * KTOT + k0 + c4);
        }
        CP_COMMIT();
    };

    auto loadB = [&](int c) {
        const int k0 = c * 32;
        if (MODE == 0) {
            #pragma unroll
            for (int i = 0; i < 2; i++) {
                int e = tid + i * 256;
                int kr = e >> 4, n4 = (e & 15) * 4;
                bR[i] = *(const float4*)(Xp + (size_t)(k0 + kr) * N + n0 + n4);
            }
        } else {
            const int crel0 = k0 >> 2;
            #pragma unroll
            for (int i = 0; i < 8; i++) {
                int e = tid + i * 256;
                int ch = e >> 8, row = (e >> 7) & 1, col = e & 127;
                bS[i] = Xp[(size_t)(crel0 + ch) * HW
                           + (2 * y2 + row) * IW + 2 * xb + col];
            }
        }
    };

    auto storeB = [&](int buf) {
        uint32_t* Bs = (uint32_t*)(sm + buf * BUFL + AFL);
        if (MODE == 0) {
            #pragma unroll
            for (int i = 0; i < 2; i++) {
                int e = tid + i * 256;
                int kr = e >> 4, n4 = (e & 15) * 4;
                uint4 v;
                v.x = f2tf32(bR[i].x); v.y = f2tf32(bR[i].y);
                v.z = f2tf32(bR[i].z); v.w = f2tf32(bR[i].w);
                *(uint4*)(Bs + kr * 68 + n4) = v;
            }
        } else {
            #pragma unroll
            for (int i = 0; i < 8; i++) {
                int e = tid + i * 256;
                int ch = e >> 8, row = (e >> 7) & 1, col = e & 127;
                int k = ch * 4 + row * 2 + (col & 1);
                int n = col >> 1;
                Bs[k * 68 + n] = f2tf32(bS[i]);
            }
        }
    };

    auto compute = [&](int buf) {
        const uint32_t* As = (const uint32_t*)(sm + buf * BUFL);
        const uint32_t* Bs = As + AFL;
        #pragma unroll
        for (int ks = 0; ks < 4; ks++) {
            uint32_t a[MT][4], b[NTW][2];
            #pragma unroll
            for (int i = 0; i < MT; i++) {
                const uint32_t* p = As + (wm * 48 + i * 16 + g) * 36 + ks * 8 + tig;
                a[i][0] = p[0];
                a[i][1] = p[8 * 36];
                a[i][2] = p[4];
                a[i][3] = p[8 * 36 + 4];
            }
            #pragma unroll
            for (int j = 0; j < NTW; j++) {
                const uint32_t* p = Bs + (ks * 8 + tig) * 68 + wn * WN + j * 8 + g;
                b[j][0] = p[0];
                b[j][1] = p[4 * 68];
            }
            #pragma unroll
            for (int i = 0; i < MT; i++)
                #pragma unroll
                for (int j = 0; j < NTW; j++)
                    mma8(acc[i][j], a[i], b[j]);
        }
    };

    loadA(0, 0);
    loadB(0);
    storeB(0);
    CP_WAIT0();
    __syncthreads();
    for (int c = 0; c < NCH; c++) {
        if (c + 1 < NCH) { loadA(c + 1, (c + 1) & 1); loadB(c + 1); }
        compute(c & 1);
        if (c + 1 < NCH) {
            storeB((c + 1) & 1);
            CP_WAIT0();
            __syncthreads();
        }
    }

    const int mb = wm * 48;
    const int nb = n0 + wn * WN;
    #pragma unroll
    for (int i = 0; i < MT; i++) {
        int r0 = mb + i * 16 + g;
        float b0 = 0.f, b1 = 0.f;
        if (BIAS) { b0 = bp[r0]; b1 = bp[r0 + 8]; }
        #pragma unroll
        for (int j = 0; j < NTW; j++) {
            int nc = nb + j * 8 + tig * 2;
            *(float2*)(Yp + (size_t)r0 * N + nc) =
                make_float2(acc[i][j][0] + b0, acc[i][j][1] + b0);
            *(float2*)(Yp + (size_t)(r0 + 8) * N + nc) =
                make_float2(acc[i][j][2] + b1, acc[i][j][3] + b1);
        }
    }
}

// ---------------- attn-M: per window, M_h = scale * K^T V -> g_Ms ----------------
constexpr int KS_F = 192 * 17;

__global__ __launch_bounds__(256, 4) void attn_m_kernel()
{
    __shared__ float ks[KS_F];
    __shared__ float vs[KS_F];

    const int w = blockIdx.x;
    const int b  = w >> 10;
    const int wl = w & 1023;
    const int wy = wl >> 5, wx = wl & 31;
    const int tid = threadIdx.x;

    const float* kvb = g_kv + (size_t)b * CDIM * HW2;
    #pragma unroll
    for (int i = 0; i < 12; i++) {
        int e = tid + i * 256;
        int ch = e >> 4, t = e & 15;
        int y2 = wy * 4 + (t >> 2), x2 = wx * 4 + (t & 3);
        size_t off = (size_t)ch * HW2 + y2 * W2 + x2;
        ks[ch * 17 + t] = kvb[off];
        vs[ch * 17 + t] = kvb[off + (size_t)CQ * HW2];
    }
    __syncthreads();

    const int h = tid >> 5, lane = tid & 31;
    const int e0 = (lane >> 2) * 3, d0 = (lane & 3) * 6;
    float acc[3][6] = {};
    const float* kp = ks + (h * 24 + e0) * 17;
    const float* vp = vs + (h * 24 + d0) * 17;
    #pragma unroll
    for (int t = 0; t < 16; t++) {
        float kk[3], vv[6];
        #pragma unroll
        for (int i = 0; i < 3; i++) kk[i] = kp[i * 17 + t];
        #pragma unroll
        for (int j = 0; j < 6; j++) vv[j] = vp[j * 17 + t];
        #pragma unroll
        for (int i = 0; i < 3; i++)
            #pragma unroll
            for (int j = 0; j < 6; j++)
                acc[i][j] = fmaf(kk[i], vv[j], acc[i][j]);
    }
    float* mo = g_Ms + (size_t)w * MS_W;
    #pragma unroll
    for (int i = 0; i < 3; i++)
        #pragma unroll
        for (int j = 0; j < 6; j++)
            mo[(e0 + i) * 192 + h * 24 + d0 + j] = acc[i][j] * ATT_SCALE;
}

// ---------------- fused attn-phase3 + proj: out[px] = P * (q[px] . M_w) + b ----
// One 512-thread CTA per window: builds feat[192][64] in smem (B operand),
// then full-M (384) GEMM with A pipelined via cp.async. No feat gmem traffic.
constexpr int FP_AFL  = 384 * 32;     // A floats per chunk (fragment order)
constexpr int FP_FEAT = 192 * 68;
constexpr int FP_QS   = 64 * 193;
constexpr int FP_SMEM = (2 * FP_AFL + FP_FEAT + FP_QS + MS_W) * 4;  // 218368 B

__global__ __launch_bounds__(512, 1) void fused_proj_kernel(
    const float* __restrict__ Wt,     // g_pw, fragment order, BM=384, K=192
    const float* __restrict__ bias, float* __restrict__ out)
{
    extern __shared__ __align__(16) float sm[];
    const uint32_t sbase = smem_u32(sm);
    float* feat = sm + 2 * FP_AFL;
    float* qs   = feat + FP_FEAT;
    float* ms   = qs + FP_QS;

    const int w = blockIdx.x;
    const int b  = w >> 10;
    const int wl = w & 1023;
    const int wy = wl >> 5, wx = wl & 31;
    const int tid = threadIdx.x, wid = tid >> 5, lane = tid & 31;

    auto loadA = [&](int c, int buf) {
        const float* src = Wt + (size_t)c * FP_AFL;
        const uint32_t dst = sbase + (uint32_t)buf * FP_AFL * 4;
        #pragma unroll
        for (int i = 0; i < 6; i++) {
            int e = tid + i * 512;
            cp_async16(dst + e * 16, src + e * 4);
        }
        CP_COMMIT();
    };
    loadA(0, 0);
    loadA(1, 1);

    // q tile -> qs[p][ch] pitch 193 (float4 over x)
    const float* qb = g_qfeat + (size_t)b * CQ * HW;
    #pragma unroll
    for (int i = 0; i < 6; i++) {
        int e = tid + i * 512;
        int ch = e >> 4, pq = e & 15, p = pq * 4;
        int y = wy * 8 + (p >> 3), x = wx * 8 + (p & 7);
        float4 v = *(const float4*)(qb + (size_t)ch * HW + y * IW + x);
        float* d = qs + p * 193 + ch;
        d[0] = v.x; d[193] = v.y; d[2 * 193] = v.z; d[3 * 193] = v.w;
    }
    // Ms -> smem
    const float* msg = g_Ms + (size_t)w * MS_W;
    #pragma unroll
    for (int i = 0; i < 9; i++) {
        int e = tid + i * 512;
        ms[e] = msg[e];
    }
    __syncthreads();

    // ---- phase A: feat[h*24+d][p] = sum_e q[p][h*24+e] * M[e][h][d] ----
    {
        const int h = tid >> 6;        // 0..7
        const int p = tid & 63;
        float acc[24] = {};
        const float* qp = qs + p * 193 + h * 24;
        const float* mp = ms + h * 24;
        #pragma unroll
        for (int e = 0; e < 24; e++) {
            float qv = qp[e];
            const float* mrow = mp + e * 192;
            #pragma unroll
            for (int db = 0; db < 6; db++) {
                float4 mv = *(const float4*)(mrow + db * 4);
                acc[db * 4 + 0] = fmaf(qv, mv.x, acc[db * 4 + 0]);
                acc[db * 4 + 1] = fmaf(qv, mv.y, acc[db * 4 + 1]);
                acc[db * 4 + 2] = fmaf(qv, mv.z, acc[db * 4 + 2]);
                acc[db * 4 + 3] = fmaf(qv, mv.w, acc[db * 4 + 3]);
            }
        }
        #pragma unroll
        for (int d = 0; d < 24; d++)
            feat[(h * 24 + d) * 68 + p] = acc[d];
    }
    __syncthreads();

    // ---- GEMM: 16 warps (8 M x 2 N), warp tile 48x32, K=192 in 6 chunks ----
    const int wm = wid >> 1, wn = wid & 1;
    const int g = lane >> 2, tig = lane & 3;
    float acc[3][4][4] = {};

    for (int c = 0; c < 6; c++) {
        // chunk c's group must be complete. For c<5 two groups are pending
        // (c, c+1) so wait_group 1 drains group c; at c==5 only group 5 is
        // pending -> must use wait_group 0 (WAIT1 would NOT guarantee it).
        if (c < 5) CP_WAIT1(); else CP_WAIT0();
        __syncthreads();
        {
            const uint32_t* As = (const uint32_t*)(sm + (c & 1) * FP_AFL);
            const float*    Bf = feat + c * 32 * 68;
            #pragma unroll
            for (int ks = 0; ks < 4; ks++) {
                uint32_t a[3][4], bfr[4][2];
                #pragma unroll
                for (int i = 0; i < 3; i++) {
                    uint4 v = *(const uint4*)(As + (((wm * 3 + i) * 4 + ks) * 32 + lane) * 4);
                    a[i][0] = v.x; a[i][1] = v.y; a[i][2] = v.z; a[i][3] = v.w;
                }
                #pragma unroll
                for (int j = 0; j < 4; j++) {
                    const float* p = Bf + (ks * 8 + tig) * 68 + wn * 32 + j * 8 + g;
                    bfr[j][0] = f2tf32(p[0]);
                    bfr[j][1] = f2tf32(p[4 * 68]);
                }
                #pragma unroll
                for (int i = 0; i < 3; i++)
                    #pragma unroll
                    for (int j = 0; j < 4; j++)
                        mma8(acc[i][j], a[i], bfr[j]);
            }
        }
        __syncthreads();
        if (c + 2 < 6) loadA(c + 2, c & 1);
    }

    // ---- epilogue: write out[b][384][y][x] ----
    #pragma unroll
    for (int i = 0; i < 3; i++) {
        int r0 = wm * 48 + i * 16 + g;
        float b0 = bias[r0], b1 = bias[r0 + 8];
        #pragma unroll
        for (int j = 0; j < 4; j++) {
            int px = wn * 32 + j * 8 + tig * 2;
            int y = wy * 8 + (px >> 3), x = wx * 8 + (px & 7);
            float* o0 = out + ((size_t)b * CDIM + r0) * HW + y * IW + x;
            *(float2*)o0 = make_float2(acc[i][j][0] + b0, acc[i][j][1] + b0);
            float* o1 = o0 + (size_t)8 * HW;
            *(float2*)o1 = make_float2(acc[i][j][2] + b1, acc[i][j][3] + b1);
        }
    }
}

// ---------------- launch ----------------
extern "C" void kernel_launch(void* const* d_in, const int* in_sizes, int n_in,
                              void* d_out, int out_size) {
    const float* x      = (const float*)d_in[0];
    const float* q_w    = (const float*)d_in[1];
    const float* kv_w   = (const float*)d_in[2];
    const float* proj_w = (const float*)d_in[3];
    const float* proj_b = (const float*)d_in[4];
    float* out = (float*)d_out;

    float *qf, *kv, *we, *qw, *pw;
    cudaGetSymbolAddress((void**)&qf, g_qfeat);
    cudaGetSymbolAddress((void**)&kv, g_kv);
    cudaGetSymbolAddress((void**)&we, g_We);
    cudaGetSymbolAddress((void**)&qw, g_qw);
    cudaGetSymbolAddress((void**)&pw, g_pw);

    auto kq = mma_gemm<4, 384, 0, 192, false>;   // q:  BM=192, K=384
    auto kk = mma_gemm<2, 384, 1,  96, false>;   // kv: BM=96,  K=384, DWT gather

    const int smem_q  = 2 * (192 * 36 + 32 * 68) * 4;  // 72704
    const int smem_kv = 2 * ( 96 * 36 + 32 * 68) * 4;  // 45056
    cudaFuncSetAttribute(kq, cudaFuncAttributeMaxDynamicSharedMemorySize, smem_q);
    cudaFuncSetAttribute(kk, cudaFuncAttributeMaxDynamicSharedMemorySize, smem_kv);
    cudaFuncSetAttribute(fused_proj_kernel, cudaFuncAttributeMaxDynamicSharedMemorySize, FP_SMEM);

    prep_we_kernel<<<(CDIM * CDIM + 255) / 256, 256>>>(kv_w);
    prep_cvt_kernel<<<(CQ * CDIM + 255) / 256, 256>>>(q_w, qw, CQ * CDIM);
    prep_arrange<384, 192><<<(CDIM * CQ + 255) / 256, 256>>>(proj_w, pw, CDIM);

    kq<<<dim3(HW / 64, 1, NB),      256, smem_q >>>(qw, x, qf, nullptr, HW);
    kk<<<dim3(HW2 / 64, 1, NB * 4), 256, smem_kv>>>(we, x, kv, nullptr, HW2);
    attn_m_kernel<<<NWIN, 256>>>();
    fused_proj_kernel<<<NWIN, 512, FP_SMEM>>>(pw, proj_b, out);
}

// round 12
// speedup vs baseline: 1.1349x; 1.1349x over previous
#include <cuda_runtime.h>
#include <cstdint>

// ---------------- problem constants ----------------
#define NB 4
#define CDIM 384
#define CQ 192
#define IH 256
#define IW 256
#define H2 128
#define W2 128
#define NHEADS 8
#define HD 24
#define ATT_SCALE 0.2041241452319315f   // 24^-0.5

constexpr int HW  = IH * IW;   // 65536
constexpr int HW2 = H2 * W2;   // 16384

// ---------------- scratch (device globals; no runtime alloc) ----------------
__device__ float g_We[CDIM * CDIM];          // DWT-folded kv weights, tf32-rounded
__device__ float g_qw[CQ * CDIM];            // q weights, tf32-rounded
__device__ float g_pw[CDIM * CQ];            // proj weights, tf32-rounded
__device__ float g_qfeat[(size_t)NB * CQ * HW];
__device__ float g_kv[(size_t)NB * CDIM * HW2];
__device__ float g_feat[(size_t)NB * CQ * HW];

// ---------------- helpers ----------------
__device__ __forceinline__ uint32_t f2tf32(float f) {
    uint32_t r;
    asm("cvt.rna.tf32.f32 %0, %1;" : "=r"(r) : "f"(f));
    return r;
}
__device__ __forceinline__ uint32_t smem_u32(const void* p) {
    uint32_t a;
    asm("{ .reg .u64 t; cvta.to.shared.u64 t, %1; cvt.u32.u64 %0, t; }" : "=r"(a) : "l"(p));
    return a;
}
__device__ __forceinline__ void cp_async16(uint32_t dst, const float* src) {
    asm volatile("cp.async.ca.shared.global [%0], [%1], 16;"
                 :: "r"(dst), "l"(__cvta_generic_to_global(src)));
}
#define CP_COMMIT() asm volatile("cp.async.commit_group;" ::: "memory")
#define CP_WAIT0()  asm volatile("cp.async.wait_group 0;"  ::: "memory")

// m16n8k8 tf32 mma (baseline PTX, sm_80+)
__device__ __forceinline__ void mma8(float* c, const uint32_t* a, const uint32_t* b) {
    asm volatile(
        "mma.sync.aligned.m16n8k8.row.col.f32.tf32.tf32.f32 "
        "{%0,%1,%2,%3}, {%4,%5,%6,%7}, {%8,%9}, {%0,%1,%2,%3};"
        : "+f"(c[0]), "+f"(c[1]), "+f"(c[2]), "+f"(c[3])
        : "r"(a[0]), "r"(a[1]), "r"(a[2]), "r"(a[3]), "r"(b[0]), "r"(b[1]));
}

// ---------------- prep: fold Haar DWT into kv weights (tf32-rounded) ----------------
__global__ void prep_we_kernel(const float* __restrict__ kvw) {
    int idx = blockIdx.x * blockDim.x + threadIdx.x;
    if (idx >= CDIM * CDIM) return;
    int ch  = idx / CDIM;
    int rem = idx - ch * CDIM;
    int c4  = rem & ~3;
    int pos = rem & 3;
    const float* w = kvw + (size_t)ch * CDIM + c4;
    float a = w[0], b = w[1], c = w[2], d = w[3];
    float r;
    if      (pos == 0) r = 0.5f * ( a - b - c + d);
    else if (pos == 1) r = 0.5f * ( a - b + c - d);
    else if (pos == 2) r = 0.5f * ( a + b - c - d);
    else               r = 0.5f * ( a + b + c + d);
    g_We[idx] = __uint_as_float(f2tf32(r));
}

// ---------------- prep: tf32-round a weight matrix ----------------
__global__ void prep_cvt_kernel(const float* __restrict__ src, float* __restrict__ dst, int n) {
    int i = blockIdx.x * blockDim.x + threadIdx.x;
    if (i < n) dst[i] = __uint_as_float(f2tf32(src[i]));
}

// ---------------- tf32 mma.sync GEMM: Y[m,n] = sum_k W[m,k] X[k,n] (+bias) ----------------
// A (pre-tf32 weights): cp.async gmem->smem [BM][36]. B: register-staged, smem [32][68].
// 2-stage pipeline, 2 CTA/SM.  (Proven R7 core — 1011us build.)
template<int WARPS_M, int KTOT, int MODE, int MTOT, bool BIAS>
__global__ __launch_bounds__(256, 2) void mma_gemm(
    const float* __restrict__ Wt, const float* __restrict__ X,
    float* __restrict__ Y, const float* __restrict__ bias, int N)
{
    constexpr int BM      = 48 * WARPS_M;
    constexpr int WARPS_N = 8 / WARPS_M;
    constexpr int WN      = 64 / WARPS_N;
    constexpr int NTW     = WN / 8;
    constexpr int MT      = 3;
    constexpr int NCH     = KTOT / 32;
    constexpr int ANF     = BM / 32;
    constexpr int AFL     = BM * 36;
    constexpr int BUFL    = AFL + 32 * 68;

    extern __shared__ __align__(16) float sm[];
    const uint32_t sbase = smem_u32(sm);
    const int tid = threadIdx.x, wid = tid >> 5, lane = tid & 31;
    const int wm = wid / WARPS_N, wn = wid % WARPS_N;
    const int g = lane >> 2, tig = lane & 3;

    const float *Wp, *Xp;
    float* Yp;
    const float* bp = bias;
    int y2 = 0, xb = 0;
    const int n0 = blockIdx.x * 64;

    if (MODE == 0) {
        int b = blockIdx.z, moff = blockIdx.y * BM;
        Wp = Wt + (size_t)moff * KTOT;
        Xp = X + (size_t)b * KTOT * N;
        Yp = Y + ((size_t)b * MTOT + moff) * N;
        if (BIAS) bp = bias + moff;
    } else {
        int b = blockIdx.z >> 2, gg = blockIdx.z & 3;
        Wp = Wt + (size_t)gg * 96 * CDIM;
        Xp = X + ((size_t)b * CDIM + gg * 96) * HW;
        Yp = Y + ((size_t)b * CDIM + gg * 96) * HW2;
        y2 = n0 >> 7; xb = n0 & 127;
    }

    float acc[MT][NTW][4] = {};
    float4 bR[2];
    float  bS[8];

    auto loadA = [&](int c, int buf) {
        const int k0 = c * 32;
        const uint32_t As = sbase + (uint32_t)buf * BUFL * 4;
        #pragma unroll
        for (int i = 0; i < ANF; i++) {
            int e = tid + i * 256;
            int m = e >> 3, c4 = (e & 7) * 4;
            cp_async16(As + (m * 36 + c4) * 4, Wp + (size_t)m * KTOT + k0 + c4);
        }
        CP_COMMIT();
    };

    auto loadB = [&](int c) {
        const int k0 = c * 32;
        if (MODE == 0) {
            #pragma unroll
            for (int i = 0; i < 2; i++) {
                int e = tid + i * 256;
                int kr = e >> 4, n4 = (e & 15) * 4;
                bR[i] = *(const float4*)(Xp + (size_t)(k0 + kr) * N + n0 + n4);
            }
        } else {
            const int crel0 = k0 >> 2;
            #pragma unroll
            for (int i = 0; i < 8; i++) {
                int e = tid + i * 256;
                int ch = e >> 8, row = (e >> 7) & 1, col = e & 127;
                bS[i] = Xp[(size_t)(crel0 + ch) * HW
                           + (2 * y2 + row) * IW + 2 * xb + col];
            }
        }
    };

    auto storeB = [&](int buf) {
        uint32_t* Bs = (uint32_t*)(sm + buf * BUFL + AFL);
        if (MODE == 0) {
            #pragma unroll
            for (int i = 0; i < 2; i++) {
                int e = tid + i * 256;
                int kr = e >> 4, n4 = (e & 15) * 4;
                uint4 v;
                v.x = f2tf32(bR[i].x); v.y = f2tf32(bR[i].y);
                v.z = f2tf32(bR[i].z); v.w = f2tf32(bR[i].w);
                *(uint4*)(Bs + kr * 68 + n4) = v;
            }
        } else {
            #pragma unroll
            for (int i = 0; i < 8; i++) {
                int e = tid + i * 256;
                int ch = e >> 8, row = (e >> 7) & 1, col = e & 127;
                int k = ch * 4 + row * 2 + (col & 1);
                int n = col >> 1;
                Bs[k * 68 + n] = f2tf32(bS[i]);
            }
        }
    };

    auto compute = [&](int buf) {
        const uint32_t* As = (const uint32_t*)(sm + buf * BUFL);
        const uint32_t* Bs = As + AFL;
        #pragma unroll
        for (int ks = 0; ks < 4; ks++) {
            uint32_t a[MT][4], b[NTW][2];
            #pragma unroll
            for (int i = 0; i < MT; i++) {
                const uint32_t* p = As + (wm * 48 + i * 16 + g) * 36 + ks * 8 + tig;
                a[i][0] = p[0];
                a[i][1] = p[8 * 36];
                a[i][2] = p[4];
                a[i][3] = p[8 * 36 + 4];
            }
            #pragma unroll
            for (int j = 0; j < NTW; j++) {
                const uint32_t* p = Bs + (ks * 8 + tig) * 68 + wn * WN + j * 8 + g;
                b[j][0] = p[0];
                b[j][1] = p[4 * 68];
            }
            #pragma unroll
            for (int i = 0; i < MT; i++)
                #pragma unroll
                for (int j = 0; j < NTW; j++)
                    mma8(acc[i][j], a[i], b[j]);
        }
    };

    loadA(0, 0);
    loadB(0);
    storeB(0);
    CP_WAIT0();
    __syncthreads();
    for (int c = 0; c < NCH; c++) {
        if (c + 1 < NCH) { loadA(c + 1, (c + 1) & 1); loadB(c + 1); }
        compute(c & 1);
        if (c + 1 < NCH) {
            storeB((c + 1) & 1);
            CP_WAIT0();
            __syncthreads();
        }
    }

    const int mb = wm * 48;
    const int nb = n0 + wn * WN;
    #pragma unroll
    for (int i = 0; i < MT; i++) {
        int r0 = mb + i * 16 + g;
        float b0 = 0.f, b1 = 0.f;
        if (BIAS) { b0 = bp[r0]; b1 = bp[r0 + 8]; }
        #pragma unroll
        for (int j = 0; j < NTW; j++) {
            int nc = nb + j * 8 + tig * 2;
            *(float2*)(Yp + (size_t)r0 * N + nc) =
                make_float2(acc[i][j][0] + b0, acc[i][j][1] + b0);
            *(float2*)(Yp + (size_t)(r0 + 8) * N + nc) =
                make_float2(acc[i][j][2] + b1, acc[i][j][3] + b1);
        }
    }
}

// ---------------- attention: bilinear, register-blocked (proven R7 core) -----
// Phase 2: M[h] = scale*K^T V (3e x 6d per thread), k/v in smem.
// Phase 3: feat = q*M (4px x 12d per thread), q direct from gmem (L2), Ms smem.
constexpr int KS_F = 192 * 17;
constexpr int MS_F = 24 * 200;
constexpr int ATTN_SMEM = (2 * KS_F + MS_F) * 4;   // 45312 B

__global__ __launch_bounds__(256, 3) void attn_kernel()
{
    extern __shared__ float sm[];
    float* ks = sm;
    float* vs = ks + KS_F;
    float* Ms = vs + KS_F;

    const int w = blockIdx.x;
    const int b  = w >> 10;
    const int wl = w & 1023;
    const int wy = wl >> 5, wx = wl & 31;
    const int tid = threadIdx.x;

    const float* kvb = g_kv + (size_t)b * CDIM * HW2;
    #pragma unroll
    for (int i = 0; i < 12; i++) {
        int e = tid + i * 256;
        int ch = e >> 4, t = e & 15;
        int y2 = wy * 4 + (t >> 2), x2 = wx * 4 + (t & 3);
        size_t off = (size_t)ch * HW2 + y2 * W2 + x2;
        ks[ch * 17 + t] = kvb[off];
        vs[ch * 17 + t] = kvb[off + (size_t)CQ * HW2];
    }
    __syncthreads();

    {
        const int h = tid >> 5, lane = tid & 31;
        const int e0 = (lane >> 2) * 3, d0 = (lane & 3) * 6;
        float acc[3][6] = {};
        const float* kp = ks + (h * 24 + e0) * 17;
        const float* vp = vs + (h * 24 + d0) * 17;
        #pragma unroll
        for (int t = 0; t < 16; t++) {
            float kk[3], vv[6];
            #pragma unroll
            for (int i = 0; i < 3; i++) kk[i] = kp[i * 17 + t];
            #pragma unroll
            for (int j = 0; j < 6; j++) vv[j] = vp[j * 17 + t];
            #pragma unroll
            for (int i = 0; i < 3; i++)
                #pragma unroll
                for (int j = 0; j < 6; j++)
                    acc[i][j] = fmaf(kk[i], vv[j], acc[i][j]);
        }
        #pragma unroll
        for (int i = 0; i < 3; i++)
            #pragma unroll
            for (int j = 0; j < 6; j++)
                Ms[(e0 + i) * 200 + h * 25 + d0 + j] = acc[i][j] * ATT_SCALE;
    }
    __syncthreads();

    {
        const int q4 = tid >> 4;
        const int h  = (tid >> 1) & 7;
        const int dh = tid & 1;
        const int p0 = q4 * 4;
        const int y = wy * 8 + (p0 >> 3), x = wx * 8 + (p0 & 7);
        float acc[4][12] = {};
        const float* qp = g_qfeat + ((size_t)b * CQ + h * 24) * HW + y * IW + x;
        const float* mp = Ms + h * 25 + dh * 12;
        #pragma unroll
        for (int e = 0; e < 24; e++) {
            float4 qv = *(const float4*)(qp + (size_t)e * HW);
            float q0 = qv.x, q1 = qv.y, q2 = qv.z, q3 = qv.w;
            #pragma unroll
            for (int j = 0; j < 12; j++) {
                float mv = mp[e * 200 + j];
                acc[0][j] = fmaf(q0, mv, acc[0][j]);
                acc[1][j] = fmaf(q1, mv, acc[1][j]);
                acc[2][j] = fmaf(q2, mv, acc[2][j]);
                acc[3][j] = fmaf(q3, mv, acc[3][j]);
            }
        }
        float* fb = g_feat + ((size_t)b * CQ + h * 24 + dh * 12) * HW + y * IW + x;
        #pragma unroll
        for (int j = 0; j < 12; j++) {
            *(float4*)(fb + (size_t)j * HW) =
                make_float4(acc[0][j], acc[1][j], acc[2][j], acc[3][j]);
        }
    }
}

// ---------------- launch: fork q / kv onto parallel streams ----------------
extern "C" void kernel_launch(void* const* d_in, const int* in_sizes, int n_in,
                              void* d_out, int out_size) {
    const float* x      = (const float*)d_in[0];
    const float* q_w    = (const float*)d_in[1];
    const float* kv_w   = (const float*)d_in[2];
    const float* proj_w = (const float*)d_in[3];
    const float* proj_b = (const float*)d_in[4];
    float* out = (float*)d_out;

    float *qf, *kv, *ft, *we, *qw, *pw;
    cudaGetSymbolAddress((void**)&qf, g_qfeat);
    cudaGetSymbolAddress((void**)&kv, g_kv);
    cudaGetSymbolAddress((void**)&ft, g_feat);
    cudaGetSymbolAddress((void**)&we, g_We);
    cudaGetSymbolAddress((void**)&qw, g_qw);
    cudaGetSymbolAddress((void**)&pw, g_pw);

    auto kq = mma_gemm<4, 384, 0, 192, false>;   // q:    BM=192, K=384
    auto kk = mma_gemm<2, 384, 1,  96, false>;   // kv:   BM=96,  K=384, DWT gather
    auto kp = mma_gemm<4, 192, 0, 384, true>;    // proj: 2 x BM=192, K=192, bias

    const int smem_q  = 2 * (192 * 36 + 32 * 68) * 4;  // 72704
    const int smem_kv = 2 * ( 96 * 36 + 32 * 68) * 4;  // 45056
    const int smem_pj = smem_q;

    // one-time setup (outside capture: first call is the correctness run)
    static bool init_done = false;
    static cudaStream_t s1;
    static cudaEvent_t evFork, evJoin;
    if (!init_done) {
        cudaFuncSetAttribute(kq, cudaFuncAttributeMaxDynamicSharedMemorySize, smem_q);
        cudaFuncSetAttribute(kk, cudaFuncAttributeMaxDynamicSharedMemorySize, smem_kv);
        cudaFuncSetAttribute(kp, cudaFuncAttributeMaxDynamicSharedMemorySize, smem_pj);
        cudaFuncSetAttribute(attn_kernel, cudaFuncAttributeMaxDynamicSharedMemorySize, ATTN_SMEM);
        cudaStreamCreateWithFlags(&s1, cudaStreamNonBlocking);
        cudaEventCreateWithFlags(&evFork, cudaEventDisableTiming);
        cudaEventCreateWithFlags(&evJoin, cudaEventDisableTiming);
        init_done = true;
    }

    // prep (stream 0)
    prep_we_kernel<<<(CDIM * CDIM + 255) / 256, 256>>>(kv_w);
    prep_cvt_kernel<<<(CQ * CDIM + 255) / 256, 256>>>(q_w, qw, CQ * CDIM);
    prep_cvt_kernel<<<(CDIM * CQ + 255) / 256, 256>>>(proj_w, pw, CDIM * CQ);

    // fork: kv on s1 concurrent with q on stream 0
    cudaEventRecord(evFork, 0);
    cudaStreamWaitEvent(s1, evFork, 0);
    kk<<<dim3(HW2 / 64, 1, NB * 4), 256, smem_kv, s1>>>(we, x, kv, nullptr, HW2);
    cudaEventRecord(evJoin, s1);

    kq<<<dim3(HW / 64, 1, NB), 256, smem_q>>>(qw, x, qf, nullptr, HW);

    // join: attn needs both qfeat (stream 0) and kv (s1)
    cudaStreamWaitEvent(0, evJoin, 0);
    attn_kernel<<<NB * 1024, 256, ATTN_SMEM>>>();
    kp<<<dim3(HW / 64, 2, NB), 256, smem_pj>>>(pw, ft, out, proj_b, HW);
}